// round 5
// baseline (speedup 1.0000x reference)
#include <cuda_runtime.h>
#include <math.h>
#include <stdint.h>

// Problem constants (fixed by the dataset)
#define NN 50000
#define FF 128
#define EE 800000
#define CC 10

#define SCAN_B 1024
#define SCAN_NB ((NN + SCAN_B - 1) / SCAN_B)   // 49

// ---------------- scratch (static device globals; no allocation) ----------
__device__ float g_W1e[FF * FF];
__device__ float g_W2e[FF * FF];
__device__ float g_dinv[NN];
__device__ int   g_count[NN];
__device__ int   g_rowptr[NN + 1];
__device__ int   g_cursor[NN];
__device__ int   g_bsum[SCAN_NB];
__device__ int   g_boff[SCAN_NB];
__device__ int   g_col[EE];
__device__ float g_colw[EE];
__device__ float g_xw[NN * FF];
__device__ float g_agg[NN * FF];

// packed dual-fp32 FMA: d.lo = fma(a.lo,b.lo,d.lo), d.hi likewise
__device__ __forceinline__ void fma2(unsigned long long& d,
                                     unsigned long long a,
                                     unsigned long long b) {
    asm("fma.rn.f32x2 %0, %1, %2, %0;" : "+l"(d) : "l"(a), "l"(b));
}

// ---------------- GRU weight evolution ------------------------------------
__global__ void gru_kernel(const float* __restrict__ W0,
                           const float* __restrict__ wih,
                           const float* __restrict__ whh,
                           const float* __restrict__ bih,
                           const float* __restrict__ bhh,
                           float* __restrict__ Wout) {
    int m = blockIdx.x;
    int f = threadIdx.x;
    __shared__ float sW[FF];
    sW[f] = W0[m * FF + f];
    __syncthreads();

    const float* wr = wih + f * FF;
    const float* wz = wih + (f + FF) * FF;
    const float* wn = wih + (f + 2 * FF) * FF;
    const float* vr = whh + f * FF;
    const float* vz = whh + (f + FF) * FF;
    const float* vn = whh + (f + 2 * FF) * FF;

    float ir = 0.f, iz = 0.f, in_ = 0.f, hr = 0.f, hz = 0.f, hn = 0.f;
#pragma unroll 8
    for (int k = 0; k < FF; k++) {
        float a = sW[k];
        ir += a * wr[k]; iz += a * wz[k]; in_ += a * wn[k];
        hr += a * vr[k]; hz += a * vz[k]; hn += a * vn[k];
    }
    ir += bih[f];          iz += bih[f + FF];     in_ += bih[f + 2 * FF];
    hr += bhh[f];          hz += bhh[f + FF];     hn += bhh[f + 2 * FF];

    float r = 1.f / (1.f + expf(-(ir + hr)));
    float z = 1.f / (1.f + expf(-(iz + hz)));
    float n = tanhf(in_ + r * hn);
    float h = sW[f];
    Wout[m * FF + f] = (1.f - z) * n + z * h;
}

// ---------------- CSR build -------------------------------------------------
__global__ void hist_kernel(const int* __restrict__ dst, int e,
                            int* __restrict__ count) {
    int i = blockIdx.x * blockDim.x + threadIdx.x;
    if (i < e) atomicAdd(&count[dst[i]], 1);
}

__global__ void __launch_bounds__(SCAN_B)
scan_blocks_kernel(const int* __restrict__ count, int* __restrict__ rowptr,
                   int* __restrict__ bsum, int n) {
    __shared__ int warp_sums[32];
    int tid = threadIdx.x;
    int lane = tid & 31, wid = tid >> 5;
    int i = blockIdx.x * SCAN_B + tid;
    int c = (i < n) ? count[i] : 0;
    int v = c;
#pragma unroll
    for (int off = 1; off < 32; off <<= 1) {
        int t = __shfl_up_sync(0xffffffffu, v, off);
        if (lane >= off) v += t;
    }
    if (lane == 31) warp_sums[wid] = v;
    __syncthreads();
    if (tid < 32) {
        int w = warp_sums[tid];
#pragma unroll
        for (int off = 1; off < 32; off <<= 1) {
            int t = __shfl_up_sync(0xffffffffu, w, off);
            if (tid >= off) w += t;
        }
        warp_sums[tid] = w;
    }
    __syncthreads();
    int incl = v + (wid > 0 ? warp_sums[wid - 1] : 0);
    if (i < n) rowptr[i] = incl - c;
    if (tid == SCAN_B - 1) bsum[blockIdx.x] = incl;
}

__global__ void scan_tops_kernel(const int* __restrict__ bsum,
                                 int* __restrict__ boff,
                                 int* __restrict__ rowptr, int n, int nb) {
    int tid = threadIdx.x;  // 64 threads
    int c = (tid < nb) ? bsum[tid] : 0;
    int v = c;
#pragma unroll
    for (int off = 1; off < 32; off <<= 1) {
        int t = __shfl_up_sync(0xffffffffu, v, off);
        if ((tid & 31) >= off) v += t;
    }
    __shared__ int w0sum;
    if (tid == 31) w0sum = v;
    __syncthreads();
    int incl = v + ((tid >= 32) ? w0sum : 0);
    if (tid < nb) boff[tid] = incl - c;
    if (tid == nb - 1) rowptr[n] = incl;
}

__global__ void __launch_bounds__(SCAN_B)
scan_add_kernel(const int* __restrict__ count, const int* __restrict__ boff,
                int* __restrict__ rowptr, int* __restrict__ cursor,
                float* __restrict__ dinv, int n) {
    int i = blockIdx.x * SCAN_B + threadIdx.x;
    if (i >= n) return;
    int r = rowptr[i] + boff[blockIdx.x];
    rowptr[i] = r;
    cursor[i] = r;
    dinv[i] = rsqrtf((float)(count[i] + 1));
}

__global__ void fill_kernel(const int* __restrict__ src,
                            const int* __restrict__ dst, int e,
                            const float* __restrict__ dinv,
                            int* __restrict__ cursor,
                            int* __restrict__ col, float* __restrict__ colw) {
    int i = blockIdx.x * blockDim.x + threadIdx.x;
    if (i >= e) return;
    int s = src[i];
    int d = dst[i];
    int idx = atomicAdd(&cursor[d], 1);
    col[idx] = s;
    colw[idx] = __ldg(dinv + s) * __ldg(dinv + d);
}

// ---------------- GEMM (fma.rn.f32x2): C[M,128] = act(A) @ W ---------------
// BM=64, BK=32, 256 threads. Column-pair-packed accumulators (8 rows x 2 pairs).
// A tile stored value-duplicated ({a,a} per element) so packed broadcast
// operands come straight from ld.shared.v2.u64 with zero packing movs.
template <bool RELU>
__global__ void __launch_bounds__(256)
gemm_nk128(const float* __restrict__ A, const float* __restrict__ W,
           float* __restrict__ C, int M) {
    __shared__ float Adup[32][128];  // [kk][2*row] duplicated pairs (16 KB)
    __shared__ float Bs[32][128];    // [kk][col]                    (16 KB)
    int tid = threadIdx.x;
    int tx = tid & 31;   // column group: cols tx*4 .. tx*4+3
    int ty = tid >> 5;   // row group:    rows ty*8 .. ty*8+7
    int row0 = blockIdx.x * 64;

    unsigned long long acc[8][2];
#pragma unroll
    for (int i = 0; i < 8; i++) { acc[i][0] = 0ull; acc[i][1] = 0ull; }

    for (int k0 = 0; k0 < 128; k0 += 32) {
        // A tile: 64x32 floats, 2 float4 per thread; store duplicated pairs
#pragma unroll
        for (int v = 0; v < 2; v++) {
            int u = tid + v * 256;
            int r = u >> 3, c4 = u & 7;
            int gr = row0 + r;
            float4 val = make_float4(0.f, 0.f, 0.f, 0.f);
            if (gr < M)
                val = *(const float4*)(A + gr * 128 + k0 + c4 * 4);
            if (RELU) {
                val.x = fmaxf(val.x, 0.f); val.y = fmaxf(val.y, 0.f);
                val.z = fmaxf(val.z, 0.f); val.w = fmaxf(val.w, 0.f);
            }
            float f[4] = {val.x, val.y, val.z, val.w};
#pragma unroll
            for (int j = 0; j < 4; j++)
                *(float2*)&Adup[c4 * 4 + j][2 * r] = make_float2(f[j], f[j]);
        }
        // B tile: 32x128 floats, 4 float4 per thread (coalesced)
#pragma unroll
        for (int v = 0; v < 4; v++) {
            int u = tid + v * 256;
            int r = u >> 5, c4 = u & 31;
            *(float4*)&Bs[r][c4 * 4] = *(const float4*)(W + (k0 + r) * 128 + c4 * 4);
        }
        __syncthreads();
#pragma unroll
        for (int kk = 0; kk < 32; kk++) {
            // b pairs: cols {4tx,4tx+1} and {4tx+2,4tx+3}, one LDS.128
            ulonglong2 b01 = *(const ulonglong2*)&Bs[kk][tx * 4];
            // a dup pairs for rows ty*8..ty*8+7 (warp-uniform -> broadcast)
            const ulonglong2* ap = (const ulonglong2*)&Adup[kk][ty * 16];
            ulonglong2 a0 = ap[0], a1 = ap[1], a2 = ap[2], a3 = ap[3];
            fma2(acc[0][0], a0.x, b01.x); fma2(acc[0][1], a0.x, b01.y);
            fma2(acc[1][0], a0.y, b01.x); fma2(acc[1][1], a0.y, b01.y);
            fma2(acc[2][0], a1.x, b01.x); fma2(acc[2][1], a1.x, b01.y);
            fma2(acc[3][0], a1.y, b01.x); fma2(acc[3][1], a1.y, b01.y);
            fma2(acc[4][0], a2.x, b01.x); fma2(acc[4][1], a2.x, b01.y);
            fma2(acc[5][0], a2.y, b01.x); fma2(acc[5][1], a2.y, b01.y);
            fma2(acc[6][0], a3.x, b01.x); fma2(acc[6][1], a3.x, b01.y);
            fma2(acc[7][0], a3.y, b01.x); fma2(acc[7][1], a3.y, b01.y);
        }
        __syncthreads();
    }
#pragma unroll
    for (int i = 0; i < 8; i++) {
        int gr = row0 + ty * 8 + i;
        if (gr < M) {
            float4 o;
            o.x = __uint_as_float((unsigned)(acc[i][0]));
            o.y = __uint_as_float((unsigned)(acc[i][0] >> 32));
            o.z = __uint_as_float((unsigned)(acc[i][1]));
            o.w = __uint_as_float((unsigned)(acc[i][1] >> 32));
            *(float4*)(C + gr * 128 + tx * 4) = o;
        }
    }
}

// ---------------- gather: agg[d] = dinv[d]^2*xw[d] + sum_e w_e * xw[col_e] --
__global__ void __launch_bounds__(256)
gather_kernel(const int* __restrict__ rowptr, const int* __restrict__ col,
              const float* __restrict__ colw, const float* __restrict__ dinv,
              const float4* __restrict__ xw, float4* __restrict__ agg, int n) {
    int warp = (blockIdx.x * blockDim.x + threadIdx.x) >> 5;
    int lane = threadIdx.x & 31;
    if (warp >= n) return;
    int beg = __ldg(rowptr + warp);
    int end = __ldg(rowptr + warp + 1);
    float di = __ldg(dinv + warp);
    float wl = di * di;
    float4 v = xw[warp * 32 + lane];
    float4 acc = make_float4(wl * v.x, wl * v.y, wl * v.z, wl * v.w);

    int e = beg;
    for (; e + 4 <= end; e += 4) {
        int s0 = __ldg(col + e + 0), s1 = __ldg(col + e + 1);
        int s2 = __ldg(col + e + 2), s3 = __ldg(col + e + 3);
        float w0 = __ldg(colw + e + 0), w1 = __ldg(colw + e + 1);
        float w2 = __ldg(colw + e + 2), w3 = __ldg(colw + e + 3);
        float4 a0 = xw[s0 * 32 + lane];
        float4 a1 = xw[s1 * 32 + lane];
        float4 a2 = xw[s2 * 32 + lane];
        float4 a3 = xw[s3 * 32 + lane];
        acc.x += w0 * a0.x + w1 * a1.x + w2 * a2.x + w3 * a3.x;
        acc.y += w0 * a0.y + w1 * a1.y + w2 * a2.y + w3 * a3.y;
        acc.z += w0 * a0.z + w1 * a1.z + w2 * a2.z + w3 * a3.z;
        acc.w += w0 * a0.w + w1 * a1.w + w2 * a2.w + w3 * a3.w;
    }
    for (; e < end; e++) {
        int s0 = __ldg(col + e);
        float w0 = __ldg(colw + e);
        float4 a0 = xw[s0 * 32 + lane];
        acc.x += w0 * a0.x; acc.y += w0 * a0.y;
        acc.z += w0 * a0.z; acc.w += w0 * a0.w;
    }
    agg[warp * 32 + lane] = acc;
}

// ---------------- final: relu -> linear(10) -> log_softmax ------------------
__global__ void __launch_bounds__(256)
final_kernel(const float* __restrict__ h, const float* __restrict__ lin_w,
             const float* __restrict__ lin_b, float* __restrict__ out, int n) {
    __shared__ float sw[CC * FF];
    __shared__ float sb[CC];
    int tid = threadIdx.x;
    for (int i = tid; i < CC * FF; i += 256) sw[i] = lin_w[i];
    if (tid < CC) sb[tid] = lin_b[tid];
    __syncthreads();

    int warp = tid >> 5, lane = tid & 31;
    int r = blockIdx.x * 8 + warp;
    if (r >= n) return;

    float4 v = *(const float4*)(h + r * 128 + lane * 4);
    v.x = fmaxf(v.x, 0.f); v.y = fmaxf(v.y, 0.f);
    v.z = fmaxf(v.z, 0.f); v.w = fmaxf(v.w, 0.f);

    float logits[CC];
#pragma unroll
    for (int c = 0; c < CC; c++) {
        float4 w = *(const float4*)(sw + c * 128 + lane * 4);
        float p = v.x * w.x + v.y * w.y + v.z * w.z + v.w * w.w;
#pragma unroll
        for (int off = 16; off > 0; off >>= 1)
            p += __shfl_xor_sync(0xffffffffu, p, off);
        logits[c] = p + sb[c];
    }
    float m = logits[0];
#pragma unroll
    for (int c = 1; c < CC; c++) m = fmaxf(m, logits[c]);
    float se = 0.f;
#pragma unroll
    for (int c = 0; c < CC; c++) se += expf(logits[c] - m);
    float lse = m + logf(se);
    if (lane == 0) {
#pragma unroll
        for (int c = 0; c < CC; c++) out[r * CC + c] = logits[c] - lse;
    }
}

// ---------------- launch ----------------------------------------------------
extern "C" void kernel_launch(void* const* d_in, const int* in_sizes, int n_in,
                              void* d_out, int out_size) {
    const float* x     = (const float*)d_in[0];
    const int*   ei    = (const int*)d_in[1];
    const float* W1    = (const float*)d_in[2];
    const float* wih1  = (const float*)d_in[3];
    const float* whh1  = (const float*)d_in[4];
    const float* bih1  = (const float*)d_in[5];
    const float* bhh1  = (const float*)d_in[6];
    const float* W2    = (const float*)d_in[7];
    const float* wih2  = (const float*)d_in[8];
    const float* whh2  = (const float*)d_in[9];
    const float* bih2  = (const float*)d_in[10];
    const float* bhh2  = (const float*)d_in[11];
    const float* lin_w = (const float*)d_in[12];
    const float* lin_b = (const float*)d_in[13];
    float* out = (float*)d_out;

    int n = in_sizes[0] / FF;   // 50000
    int e = in_sizes[1] / 2;    // 800000
    const int* src = ei;
    const int* dst = ei + e;

    float *pW1e, *pW2e, *pdinv, *pxw, *pagg, *pcolw;
    int *pcount, *prowptr, *pcursor, *pcol, *pbsum, *pboff;
    cudaGetSymbolAddress((void**)&pW1e, g_W1e);
    cudaGetSymbolAddress((void**)&pW2e, g_W2e);
    cudaGetSymbolAddress((void**)&pdinv, g_dinv);
    cudaGetSymbolAddress((void**)&pcount, g_count);
    cudaGetSymbolAddress((void**)&prowptr, g_rowptr);
    cudaGetSymbolAddress((void**)&pcursor, g_cursor);
    cudaGetSymbolAddress((void**)&pcol, g_col);
    cudaGetSymbolAddress((void**)&pcolw, g_colw);
    cudaGetSymbolAddress((void**)&pxw, g_xw);
    cudaGetSymbolAddress((void**)&pagg, g_agg);
    cudaGetSymbolAddress((void**)&pbsum, g_bsum);
    cudaGetSymbolAddress((void**)&pboff, g_boff);

    int nb = (n + SCAN_B - 1) / SCAN_B;  // 49

    // 1. evolve weights
    gru_kernel<<<FF, FF>>>(W1, wih1, whh1, bih1, bhh1, pW1e);
    gru_kernel<<<FF, FF>>>(W2, wih2, whh2, bih2, bhh2, pW2e);

    // 2. CSR build: histogram -> 3-pass scan -> fill
    cudaMemsetAsync(pcount, 0, n * sizeof(int));
    hist_kernel<<<(e + 255) / 256, 256>>>(dst, e, pcount);
    scan_blocks_kernel<<<nb, SCAN_B>>>(pcount, prowptr, pbsum, n);
    scan_tops_kernel<<<1, 64>>>(pbsum, pboff, prowptr, n, nb);
    scan_add_kernel<<<nb, SCAN_B>>>(pcount, pboff, prowptr, pcursor, pdinv, n);
    fill_kernel<<<(e + 255) / 256, 256>>>(src, dst, e, pdinv, pcursor, pcol, pcolw);

    int gemm_blocks = (n + 63) / 64;
    int ga_blocks   = (n * 32 + 255) / 256;

    // 3. layer 1
    gemm_nk128<false><<<gemm_blocks, 256>>>(x, pW1e, pxw, n);
    gather_kernel<<<ga_blocks, 256>>>(prowptr, pcol, pcolw, pdinv,
                                      (const float4*)pxw, (float4*)pagg, n);

    // 4. layer 2 (relu fused into GEMM A-load)
    gemm_nk128<true><<<gemm_blocks, 256>>>(pagg, pW2e, pxw, n);
    gather_kernel<<<ga_blocks, 256>>>(prowptr, pcol, pcolw, pdinv,
                                      (const float4*)pxw, (float4*)pagg, n);

    // 5. relu -> linear -> log_softmax
    final_kernel<<<(n + 7) / 8, 256>>>(pagg, lin_w, lin_b, out, n);
}

// round 6
// speedup vs baseline: 1.0995x; 1.0995x over previous
#include <cuda_runtime.h>
#include <math.h>
#include <stdint.h>

// Problem constants (fixed by the dataset)
#define NN 50000
#define FF 128
#define EE 800000
#define CC 10

#define SCAN_B 1024
#define SCAN_NB ((NN + SCAN_B - 1) / SCAN_B)   // 49

// ---------------- scratch (static device globals; no allocation) ----------
__device__ float g_W1e[FF * FF];
__device__ float g_W2e[FF * FF];
__device__ float g_dinv[NN];
__device__ int   g_count[NN];
__device__ int   g_rowptr[NN + 1];
__device__ int   g_cursor[NN];
__device__ int   g_bsum[SCAN_NB];
__device__ int   g_boff[SCAN_NB];
__device__ int   g_col[EE];
__device__ float g_colw[EE];
__device__ float g_xw[NN * FF];
__device__ float g_agg[NN * FF];

// packed dual-fp32 FMA: d.lo += a.lo*b.lo, d.hi += a.hi*b.hi
__device__ __forceinline__ void fma2(unsigned long long& d,
                                     unsigned long long a,
                                     unsigned long long b) {
    asm("fma.rn.f32x2 %0, %1, %2, %0;" : "+l"(d) : "l"(a), "l"(b));
}
// pack {a, a} into a u64 operand
__device__ __forceinline__ unsigned long long dup2(float a) {
    unsigned long long r;
    asm("mov.b64 %0, {%1, %1};" : "=l"(r) : "f"(a));
    return r;
}

// ---------------- GRU weight evolution ------------------------------------
__global__ void gru_kernel(const float* __restrict__ W0,
                           const float* __restrict__ wih,
                           const float* __restrict__ whh,
                           const float* __restrict__ bih,
                           const float* __restrict__ bhh,
                           float* __restrict__ Wout) {
    int m = blockIdx.x;
    int f = threadIdx.x;
    __shared__ float sW[FF];
    sW[f] = W0[m * FF + f];
    __syncthreads();

    const float* wr = wih + f * FF;
    const float* wz = wih + (f + FF) * FF;
    const float* wn = wih + (f + 2 * FF) * FF;
    const float* vr = whh + f * FF;
    const float* vz = whh + (f + FF) * FF;
    const float* vn = whh + (f + 2 * FF) * FF;

    float ir = 0.f, iz = 0.f, in_ = 0.f, hr = 0.f, hz = 0.f, hn = 0.f;
#pragma unroll 8
    for (int k = 0; k < FF; k++) {
        float a = sW[k];
        ir += a * wr[k]; iz += a * wz[k]; in_ += a * wn[k];
        hr += a * vr[k]; hz += a * vz[k]; hn += a * vn[k];
    }
    ir += bih[f];          iz += bih[f + FF];     in_ += bih[f + 2 * FF];
    hr += bhh[f];          hz += bhh[f + FF];     hn += bhh[f + 2 * FF];

    float r = 1.f / (1.f + expf(-(ir + hr)));
    float z = 1.f / (1.f + expf(-(iz + hz)));
    float n = tanhf(in_ + r * hn);
    float h = sW[f];
    Wout[m * FF + f] = (1.f - z) * n + z * h;
}

// ---------------- CSR build -------------------------------------------------
__global__ void hist_kernel(const int* __restrict__ dst, int e,
                            int* __restrict__ count) {
    int i = blockIdx.x * blockDim.x + threadIdx.x;
    if (i < e) atomicAdd(&count[dst[i]], 1);
}

__global__ void __launch_bounds__(SCAN_B)
scan_blocks_kernel(const int* __restrict__ count, int* __restrict__ rowptr,
                   int* __restrict__ bsum, int n) {
    __shared__ int warp_sums[32];
    int tid = threadIdx.x;
    int lane = tid & 31, wid = tid >> 5;
    int i = blockIdx.x * SCAN_B + tid;
    int c = (i < n) ? count[i] : 0;
    int v = c;
#pragma unroll
    for (int off = 1; off < 32; off <<= 1) {
        int t = __shfl_up_sync(0xffffffffu, v, off);
        if (lane >= off) v += t;
    }
    if (lane == 31) warp_sums[wid] = v;
    __syncthreads();
    if (tid < 32) {
        int w = warp_sums[tid];
#pragma unroll
        for (int off = 1; off < 32; off <<= 1) {
            int t = __shfl_up_sync(0xffffffffu, w, off);
            if (tid >= off) w += t;
        }
        warp_sums[tid] = w;
    }
    __syncthreads();
    int incl = v + (wid > 0 ? warp_sums[wid - 1] : 0);
    if (i < n) rowptr[i] = incl - c;
    if (tid == SCAN_B - 1) bsum[blockIdx.x] = incl;
}

__global__ void scan_tops_kernel(const int* __restrict__ bsum,
                                 int* __restrict__ boff,
                                 int* __restrict__ rowptr, int n, int nb) {
    int tid = threadIdx.x;  // 64 threads
    int c = (tid < nb) ? bsum[tid] : 0;
    int v = c;
#pragma unroll
    for (int off = 1; off < 32; off <<= 1) {
        int t = __shfl_up_sync(0xffffffffu, v, off);
        if ((tid & 31) >= off) v += t;
    }
    __shared__ int w0sum;
    if (tid == 31) w0sum = v;
    __syncthreads();
    int incl = v + ((tid >= 32) ? w0sum : 0);
    if (tid < nb) boff[tid] = incl - c;
    if (tid == nb - 1) rowptr[n] = incl;
}

__global__ void __launch_bounds__(SCAN_B)
scan_add_kernel(const int* __restrict__ count, const int* __restrict__ boff,
                int* __restrict__ rowptr, int* __restrict__ cursor,
                float* __restrict__ dinv, int n) {
    int i = blockIdx.x * SCAN_B + threadIdx.x;
    if (i >= n) return;
    int r = rowptr[i] + boff[blockIdx.x];
    rowptr[i] = r;
    cursor[i] = r;
    dinv[i] = rsqrtf((float)(count[i] + 1));
}

__global__ void fill_kernel(const int* __restrict__ src,
                            const int* __restrict__ dst, int e,
                            const float* __restrict__ dinv,
                            int* __restrict__ cursor,
                            int* __restrict__ col, float* __restrict__ colw) {
    int i = blockIdx.x * blockDim.x + threadIdx.x;
    if (i >= e) return;
    int s = src[i];
    int d = dst[i];
    int idx = atomicAdd(&cursor[d], 1);
    col[idx] = s;
    colw[idx] = __ldg(dinv + s) * __ldg(dinv + d);
}

// ---------------- GEMM: C[M,128] = act(A)[M,128] @ W[128,128] --------------
// Round-3 layout (proven conflict-free) + FFMA2 packed accumulators.
// BM=64, BK=32, 256 threads, thread tile 8 rows x 4 cols (2 col-pairs).
template <bool RELU>
__global__ void __launch_bounds__(256)
gemm_nk128(const float* __restrict__ A, const float* __restrict__ W,
           float* __restrict__ C, int M) {
    __shared__ float As[64][32];
    __shared__ float Bs[32][128];
    int tid = threadIdx.x;
    int tx = tid & 31;   // column group: cols tx*4 .. tx*4+3
    int ty = tid >> 5;   // row group:    rows ty*8 .. ty*8+7
    int row0 = blockIdx.x * 64;

    unsigned long long acc[8][2];   // [row][col-pair], packed fp32x2
#pragma unroll
    for (int i = 0; i < 8; i++) { acc[i][0] = 0ull; acc[i][1] = 0ull; }

    for (int k0 = 0; k0 < 128; k0 += 32) {
        // A tile: 64x32 floats = 512 float4 units, 2 per thread (coalesced,
        // conflict-free stores: bank = 4*c4)
#pragma unroll
        for (int v = 0; v < 2; v++) {
            int u = tid + v * 256;
            int r = u >> 3, c4 = u & 7;
            int gr = row0 + r;
            float4 val = make_float4(0.f, 0.f, 0.f, 0.f);
            if (gr < M)
                val = *(const float4*)(A + gr * 128 + k0 + c4 * 4);
            if (RELU) {
                val.x = fmaxf(val.x, 0.f); val.y = fmaxf(val.y, 0.f);
                val.z = fmaxf(val.z, 0.f); val.w = fmaxf(val.w, 0.f);
            }
            *(float4*)&As[r][c4 * 4] = val;
        }
        // B tile: 32x128 floats = 1024 float4 units, 4 per thread (coalesced)
#pragma unroll
        for (int v = 0; v < 4; v++) {
            int u = tid + v * 256;
            int r = u >> 5, c4 = u & 31;
            *(float4*)&Bs[r][c4 * 4] = *(const float4*)(W + (k0 + r) * 128 + c4 * 4);
        }
        __syncthreads();
#pragma unroll
        for (int kk = 0; kk < 32; kk++) {
            // one LDS.128 yields both packed col-pairs {b0,b1},{b2,b3}
            ulonglong2 b01 = *(const ulonglong2*)&Bs[kk][tx * 4];
#pragma unroll
            for (int i = 0; i < 8; i++) {
                unsigned long long ad = dup2(As[ty * 8 + i][kk]);  // broadcast
                fma2(acc[i][0], ad, b01.x);
                fma2(acc[i][1], ad, b01.y);
            }
        }
        __syncthreads();
    }
#pragma unroll
    for (int i = 0; i < 8; i++) {
        int gr = row0 + ty * 8 + i;
        if (gr < M) {
            float4 o;
            o.x = __uint_as_float((unsigned)(acc[i][0]));
            o.y = __uint_as_float((unsigned)(acc[i][0] >> 32));
            o.z = __uint_as_float((unsigned)(acc[i][1]));
            o.w = __uint_as_float((unsigned)(acc[i][1] >> 32));
            *(float4*)(C + gr * 128 + tx * 4) = o;
        }
    }
}

// ---------------- gather: agg[d] = dinv[d]^2*xw[d] + sum_e w_e * xw[col_e] --
__global__ void __launch_bounds__(256)
gather_kernel(const int* __restrict__ rowptr, const int* __restrict__ col,
              const float* __restrict__ colw, const float* __restrict__ dinv,
              const float4* __restrict__ xw, float4* __restrict__ agg, int n) {
    int warp = (blockIdx.x * blockDim.x + threadIdx.x) >> 5;
    int lane = threadIdx.x & 31;
    if (warp >= n) return;
    int beg = __ldg(rowptr + warp);
    int end = __ldg(rowptr + warp + 1);
    float di = __ldg(dinv + warp);
    float wl = di * di;
    float4 v = xw[warp * 32 + lane];
    float4 acc = make_float4(wl * v.x, wl * v.y, wl * v.z, wl * v.w);

    int e = beg;
    for (; e + 4 <= end; e += 4) {
        int s0 = __ldg(col + e + 0), s1 = __ldg(col + e + 1);
        int s2 = __ldg(col + e + 2), s3 = __ldg(col + e + 3);
        float w0 = __ldg(colw + e + 0), w1 = __ldg(colw + e + 1);
        float w2 = __ldg(colw + e + 2), w3 = __ldg(colw + e + 3);
        float4 a0 = xw[s0 * 32 + lane];
        float4 a1 = xw[s1 * 32 + lane];
        float4 a2 = xw[s2 * 32 + lane];
        float4 a3 = xw[s3 * 32 + lane];
        acc.x += w0 * a0.x + w1 * a1.x + w2 * a2.x + w3 * a3.x;
        acc.y += w0 * a0.y + w1 * a1.y + w2 * a2.y + w3 * a3.y;
        acc.z += w0 * a0.z + w1 * a1.z + w2 * a2.z + w3 * a3.z;
        acc.w += w0 * a0.w + w1 * a1.w + w2 * a2.w + w3 * a3.w;
    }
    for (; e < end; e++) {
        int s0 = __ldg(col + e);
        float w0 = __ldg(colw + e);
        float4 a0 = xw[s0 * 32 + lane];
        acc.x += w0 * a0.x; acc.y += w0 * a0.y;
        acc.z += w0 * a0.z; acc.w += w0 * a0.w;
    }
    agg[warp * 32 + lane] = acc;
}

// ---------------- final: relu -> linear(10) -> log_softmax ------------------
__global__ void __launch_bounds__(256)
final_kernel(const float* __restrict__ h, const float* __restrict__ lin_w,
             const float* __restrict__ lin_b, float* __restrict__ out, int n) {
    __shared__ float sw[CC * FF];
    __shared__ float sb[CC];
    int tid = threadIdx.x;
    for (int i = tid; i < CC * FF; i += 256) sw[i] = lin_w[i];
    if (tid < CC) sb[tid] = lin_b[tid];
    __syncthreads();

    int warp = tid >> 5, lane = tid & 31;
    int r = blockIdx.x * 8 + warp;
    if (r >= n) return;

    float4 v = *(const float4*)(h + r * 128 + lane * 4);
    v.x = fmaxf(v.x, 0.f); v.y = fmaxf(v.y, 0.f);
    v.z = fmaxf(v.z, 0.f); v.w = fmaxf(v.w, 0.f);

    float logits[CC];
#pragma unroll
    for (int c = 0; c < CC; c++) {
        float4 w = *(const float4*)(sw + c * 128 + lane * 4);
        float p = v.x * w.x + v.y * w.y + v.z * w.z + v.w * w.w;
#pragma unroll
        for (int off = 16; off > 0; off >>= 1)
            p += __shfl_xor_sync(0xffffffffu, p, off);
        logits[c] = p + sb[c];
    }
    float m = logits[0];
#pragma unroll
    for (int c = 1; c < CC; c++) m = fmaxf(m, logits[c]);
    float se = 0.f;
#pragma unroll
    for (int c = 0; c < CC; c++) se += expf(logits[c] - m);
    float lse = m + logf(se);
    if (lane == 0) {
#pragma unroll
        for (int c = 0; c < CC; c++) out[r * CC + c] = logits[c] - lse;
    }
}

// ---------------- launch ----------------------------------------------------
extern "C" void kernel_launch(void* const* d_in, const int* in_sizes, int n_in,
                              void* d_out, int out_size) {
    const float* x     = (const float*)d_in[0];
    const int*   ei    = (const int*)d_in[1];
    const float* W1    = (const float*)d_in[2];
    const float* wih1  = (const float*)d_in[3];
    const float* whh1  = (const float*)d_in[4];
    const float* bih1  = (const float*)d_in[5];
    const float* bhh1  = (const float*)d_in[6];
    const float* W2    = (const float*)d_in[7];
    const float* wih2  = (const float*)d_in[8];
    const float* whh2  = (const float*)d_in[9];
    const float* bih2  = (const float*)d_in[10];
    const float* bhh2  = (const float*)d_in[11];
    const float* lin_w = (const float*)d_in[12];
    const float* lin_b = (const float*)d_in[13];
    float* out = (float*)d_out;

    int n = in_sizes[0] / FF;   // 50000
    int e = in_sizes[1] / 2;    // 800000
    const int* src = ei;
    const int* dst = ei + e;

    float *pW1e, *pW2e, *pdinv, *pxw, *pagg, *pcolw;
    int *pcount, *prowptr, *pcursor, *pcol, *pbsum, *pboff;
    cudaGetSymbolAddress((void**)&pW1e, g_W1e);
    cudaGetSymbolAddress((void**)&pW2e, g_W2e);
    cudaGetSymbolAddress((void**)&pdinv, g_dinv);
    cudaGetSymbolAddress((void**)&pcount, g_count);
    cudaGetSymbolAddress((void**)&prowptr, g_rowptr);
    cudaGetSymbolAddress((void**)&pcursor, g_cursor);
    cudaGetSymbolAddress((void**)&pcol, g_col);
    cudaGetSymbolAddress((void**)&pcolw, g_colw);
    cudaGetSymbolAddress((void**)&pxw, g_xw);
    cudaGetSymbolAddress((void**)&pagg, g_agg);
    cudaGetSymbolAddress((void**)&pbsum, g_bsum);
    cudaGetSymbolAddress((void**)&pboff, g_boff);

    int nb = (n + SCAN_B - 1) / SCAN_B;  // 49

    // 1. evolve weights
    gru_kernel<<<FF, FF>>>(W1, wih1, whh1, bih1, bhh1, pW1e);
    gru_kernel<<<FF, FF>>>(W2, wih2, whh2, bih2, bhh2, pW2e);

    // 2. CSR build: histogram -> 3-pass scan -> fill
    cudaMemsetAsync(pcount, 0, n * sizeof(int));
    hist_kernel<<<(e + 255) / 256, 256>>>(dst, e, pcount);
    scan_blocks_kernel<<<nb, SCAN_B>>>(pcount, prowptr, pbsum, n);
    scan_tops_kernel<<<1, 64>>>(pbsum, pboff, prowptr, n, nb);
    scan_add_kernel<<<nb, SCAN_B>>>(pcount, pboff, prowptr, pcursor, pdinv, n);
    fill_kernel<<<(e + 255) / 256, 256>>>(src, dst, e, pdinv, pcursor, pcol, pcolw);

    int gemm_blocks = (n + 63) / 64;
    int ga_blocks   = (n * 32 + 255) / 256;

    // 3. layer 1
    gemm_nk128<false><<<gemm_blocks, 256>>>(x, pW1e, pxw, n);
    gather_kernel<<<ga_blocks, 256>>>(prowptr, pcol, pcolw, pdinv,
                                      (const float4*)pxw, (float4*)pagg, n);

    // 4. layer 2 (relu fused into GEMM A-load)
    gemm_nk128<true><<<gemm_blocks, 256>>>(pagg, pW2e, pxw, n);
    gather_kernel<<<ga_blocks, 256>>>(prowptr, pcol, pcolw, pdinv,
                                      (const float4*)pxw, (float4*)pagg, n);

    // 5. relu -> linear -> log_softmax
    final_kernel<<<(n + 7) / 8, 256>>>(pagg, lin_w, lin_b, out, n);
}

// round 9
// speedup vs baseline: 1.1242x; 1.0225x over previous
#include <cuda_runtime.h>
#include <math.h>
#include <stdint.h>

// Problem constants (fixed by the dataset)
#define NN 50000
#define FF 128
#define EE 800000
#define CC 10

#define SCAN_B 1024
#define SCAN_NB ((NN + SCAN_B - 1) / SCAN_B)   // 49

// ---------------- scratch (static device globals; no allocation) ----------
__device__ float g_W1e[FF * FF];
__device__ float g_W2e[FF * FF];
__device__ float g_dinv[NN];
__device__ int   g_count[NN];
__device__ int   g_rowptr[NN + 1];
__device__ int   g_cursor[NN];
__device__ int   g_bsum[SCAN_NB];
__device__ int   g_boff[SCAN_NB];
__device__ int   g_col[EE];
__device__ float g_colw[EE];
__device__ float g_xw[NN * FF];
__device__ float g_agg[NN * FF];

// packed dual-fp32 FMA: d.lo += a.lo*b.lo, d.hi += a.hi*b.hi
__device__ __forceinline__ void fma2(unsigned long long& d,
                                     unsigned long long a,
                                     unsigned long long b) {
    asm("fma.rn.f32x2 %0, %1, %2, %0;" : "+l"(d) : "l"(a), "l"(b));
}
// pack {a, a} into a u64 operand
__device__ __forceinline__ unsigned long long dup2(float a) {
    unsigned long long r;
    asm("mov.b64 %0, {%1, %1};" : "=l"(r) : "f"(a));
    return r;
}

// ---------------- GRU weight evolution ------------------------------------
__global__ void gru_kernel(const float* __restrict__ W0,
                           const float* __restrict__ wih,
                           const float* __restrict__ whh,
                           const float* __restrict__ bih,
                           const float* __restrict__ bhh,
                           float* __restrict__ Wout) {
    int m = blockIdx.x;
    int f = threadIdx.x;
    __shared__ float sW[FF];
    sW[f] = W0[m * FF + f];
    __syncthreads();

    const float* wr = wih + f * FF;
    const float* wz = wih + (f + FF) * FF;
    const float* wn = wih + (f + 2 * FF) * FF;
    const float* vr = whh + f * FF;
    const float* vz = whh + (f + FF) * FF;
    const float* vn = whh + (f + 2 * FF) * FF;

    float ir = 0.f, iz = 0.f, in_ = 0.f, hr = 0.f, hz = 0.f, hn = 0.f;
#pragma unroll 8
    for (int k = 0; k < FF; k++) {
        float a = sW[k];
        ir += a * wr[k]; iz += a * wz[k]; in_ += a * wn[k];
        hr += a * vr[k]; hz += a * vz[k]; hn += a * vn[k];
    }
    ir += bih[f];          iz += bih[f + FF];     in_ += bih[f + 2 * FF];
    hr += bhh[f];          hz += bhh[f + FF];     hn += bhh[f + 2 * FF];

    float r = 1.f / (1.f + expf(-(ir + hr)));
    float z = 1.f / (1.f + expf(-(iz + hz)));
    float n = tanhf(in_ + r * hn);
    float h = sW[f];
    Wout[m * FF + f] = (1.f - z) * n + z * h;
}

// ---------------- CSR build -------------------------------------------------
__global__ void hist_kernel(const int* __restrict__ dst, int e,
                            int* __restrict__ count) {
    int i = blockIdx.x * blockDim.x + threadIdx.x;
    if (i < e) atomicAdd(&count[dst[i]], 1);
}

__global__ void __launch_bounds__(SCAN_B)
scan_blocks_kernel(const int* __restrict__ count, int* __restrict__ rowptr,
                   int* __restrict__ bsum, int n) {
    __shared__ int warp_sums[32];
    int tid = threadIdx.x;
    int lane = tid & 31, wid = tid >> 5;
    int i = blockIdx.x * SCAN_B + tid;
    int c = (i < n) ? count[i] : 0;
    int v = c;
#pragma unroll
    for (int off = 1; off < 32; off <<= 1) {
        int t = __shfl_up_sync(0xffffffffu, v, off);
        if (lane >= off) v += t;
    }
    if (lane == 31) warp_sums[wid] = v;
    __syncthreads();
    if (tid < 32) {
        int w = warp_sums[tid];
#pragma unroll
        for (int off = 1; off < 32; off <<= 1) {
            int t = __shfl_up_sync(0xffffffffu, w, off);
            if (tid >= off) w += t;
        }
        warp_sums[tid] = w;
    }
    __syncthreads();
    int incl = v + (wid > 0 ? warp_sums[wid - 1] : 0);
    if (i < n) rowptr[i] = incl - c;
    if (tid == SCAN_B - 1) bsum[blockIdx.x] = incl;
}

__global__ void scan_tops_kernel(const int* __restrict__ bsum,
                                 int* __restrict__ boff,
                                 int* __restrict__ rowptr, int n, int nb) {
    int tid = threadIdx.x;  // 64 threads
    int c = (tid < nb) ? bsum[tid] : 0;
    int v = c;
#pragma unroll
    for (int off = 1; off < 32; off <<= 1) {
        int t = __shfl_up_sync(0xffffffffu, v, off);
        if ((tid & 31) >= off) v += t;
    }
    __shared__ int w0sum;
    if (tid == 31) w0sum = v;
    __syncthreads();
    int incl = v + ((tid >= 32) ? w0sum : 0);
    if (tid < nb) boff[tid] = incl - c;
    if (tid == nb - 1) rowptr[n] = incl;
}

__global__ void __launch_bounds__(SCAN_B)
scan_add_kernel(const int* __restrict__ count, const int* __restrict__ boff,
                int* __restrict__ rowptr, int* __restrict__ cursor,
                float* __restrict__ dinv, int n) {
    int i = blockIdx.x * SCAN_B + threadIdx.x;
    if (i >= n) return;
    int r = rowptr[i] + boff[blockIdx.x];
    rowptr[i] = r;
    cursor[i] = r;
    dinv[i] = rsqrtf((float)(count[i] + 1));
}

__global__ void fill_kernel(const int* __restrict__ src,
                            const int* __restrict__ dst, int e,
                            const float* __restrict__ dinv,
                            int* __restrict__ cursor,
                            int* __restrict__ col, float* __restrict__ colw) {
    int i = blockIdx.x * blockDim.x + threadIdx.x;
    if (i >= e) return;
    int s = src[i];
    int d = dst[i];
    int idx = atomicAdd(&cursor[d], 1);
    col[idx] = s;
    colw[idx] = __ldg(dinv + s) * __ldg(dinv + d);
}

// ---------------- GEMM: C[M,128] = act(A)[M,128] @ W[128,128] --------------
// BM=64, BK=32, 256 threads, FFMA2 packed accumulators (8 rows x 2 col-pairs).
template <bool RELU>
__global__ void __launch_bounds__(256)
gemm_nk128(const float* __restrict__ A, const float* __restrict__ W,
           float* __restrict__ C, int M) {
    __shared__ float As[64][32];
    __shared__ float Bs[32][128];
    int tid = threadIdx.x;
    int tx = tid & 31;   // column group: cols tx*4 .. tx*4+3
    int ty = tid >> 5;   // row group:    rows ty*8 .. ty*8+7
    int row0 = blockIdx.x * 64;

    unsigned long long acc[8][2];   // [row][col-pair], packed fp32x2
#pragma unroll
    for (int i = 0; i < 8; i++) { acc[i][0] = 0ull; acc[i][1] = 0ull; }

    for (int k0 = 0; k0 < 128; k0 += 32) {
#pragma unroll
        for (int v = 0; v < 2; v++) {
            int u = tid + v * 256;
            int r = u >> 3, c4 = u & 7;
            int gr = row0 + r;
            float4 val = make_float4(0.f, 0.f, 0.f, 0.f);
            if (gr < M)
                val = *(const float4*)(A + gr * 128 + k0 + c4 * 4);
            if (RELU) {
                val.x = fmaxf(val.x, 0.f); val.y = fmaxf(val.y, 0.f);
                val.z = fmaxf(val.z, 0.f); val.w = fmaxf(val.w, 0.f);
            }
            *(float4*)&As[r][c4 * 4] = val;
        }
#pragma unroll
        for (int v = 0; v < 4; v++) {
            int u = tid + v * 256;
            int r = u >> 5, c4 = u & 31;
            *(float4*)&Bs[r][c4 * 4] = *(const float4*)(W + (k0 + r) * 128 + c4 * 4);
        }
        __syncthreads();
#pragma unroll
        for (int kk = 0; kk < 32; kk++) {
            ulonglong2 b01 = *(const ulonglong2*)&Bs[kk][tx * 4];
#pragma unroll
            for (int i = 0; i < 8; i++) {
                unsigned long long ad = dup2(As[ty * 8 + i][kk]);  // broadcast
                fma2(acc[i][0], ad, b01.x);
                fma2(acc[i][1], ad, b01.y);
            }
        }
        __syncthreads();
    }
#pragma unroll
    for (int i = 0; i < 8; i++) {
        int gr = row0 + ty * 8 + i;
        if (gr < M) {
            float4 o;
            o.x = __uint_as_float((unsigned)(acc[i][0]));
            o.y = __uint_as_float((unsigned)(acc[i][0] >> 32));
            o.z = __uint_as_float((unsigned)(acc[i][1]));
            o.w = __uint_as_float((unsigned)(acc[i][1] >> 32));
            *(float4*)(C + gr * 128 + tx * 4) = o;
        }
    }
}

// ---------------- gather core (row accumulate in registers) -----------------
__device__ __forceinline__ float4 gather_row(const int* __restrict__ rowptr,
                                             const int* __restrict__ col,
                                             const float* __restrict__ colw,
                                             const float* __restrict__ dinv,
                                             const float4* __restrict__ xw,
                                             int row, int lane) {
    int beg = __ldg(rowptr + row);
    int end = __ldg(rowptr + row + 1);
    float di = __ldg(dinv + row);
    float wl = di * di;
    float4 v = xw[row * 32 + lane];
    float4 acc = make_float4(wl * v.x, wl * v.y, wl * v.z, wl * v.w);

    int e = beg;
    for (; e + 8 <= end; e += 8) {
        int s[8]; float w[8]; float4 a[8];
#pragma unroll
        for (int j = 0; j < 8; j++) s[j] = __ldg(col + e + j);
#pragma unroll
        for (int j = 0; j < 8; j++) w[j] = __ldg(colw + e + j);
#pragma unroll
        for (int j = 0; j < 8; j++) a[j] = xw[s[j] * 32 + lane];
#pragma unroll
        for (int j = 0; j < 8; j++) {
            acc.x += w[j] * a[j].x;
            acc.y += w[j] * a[j].y;
            acc.z += w[j] * a[j].z;
            acc.w += w[j] * a[j].w;
        }
    }
    for (; e + 4 <= end; e += 4) {
        int s0 = __ldg(col + e + 0), s1 = __ldg(col + e + 1);
        int s2 = __ldg(col + e + 2), s3 = __ldg(col + e + 3);
        float w0 = __ldg(colw + e + 0), w1 = __ldg(colw + e + 1);
        float w2 = __ldg(colw + e + 2), w3 = __ldg(colw + e + 3);
        float4 a0 = xw[s0 * 32 + lane];
        float4 a1 = xw[s1 * 32 + lane];
        float4 a2 = xw[s2 * 32 + lane];
        float4 a3 = xw[s3 * 32 + lane];
        acc.x += w0 * a0.x + w1 * a1.x + w2 * a2.x + w3 * a3.x;
        acc.y += w0 * a0.y + w1 * a1.y + w2 * a2.y + w3 * a3.y;
        acc.z += w0 * a0.z + w1 * a1.z + w2 * a2.z + w3 * a3.z;
        acc.w += w0 * a0.w + w1 * a1.w + w2 * a2.w + w3 * a3.w;
    }
    for (; e < end; e++) {
        int s0 = __ldg(col + e);
        float w0 = __ldg(colw + e);
        float4 a0 = xw[s0 * 32 + lane];
        acc.x += w0 * a0.x; acc.y += w0 * a0.y;
        acc.z += w0 * a0.z; acc.w += w0 * a0.w;
    }
    return acc;
}

// ---------------- gather (layer 1): writes agg rows -------------------------
__global__ void __launch_bounds__(256)
gather_kernel(const int* __restrict__ rowptr, const int* __restrict__ col,
              const float* __restrict__ colw, const float* __restrict__ dinv,
              const float4* __restrict__ xw, float4* __restrict__ agg, int n) {
    int warp = (blockIdx.x * blockDim.x + threadIdx.x) >> 5;
    int lane = threadIdx.x & 31;
    if (warp >= n) return;
    agg[warp * 32 + lane] = gather_row(rowptr, col, colw, dinv, xw, warp, lane);
}

// ---------------- gather (layer 2) fused with relu->linear->log_softmax -----
__global__ void __launch_bounds__(256)
gather_final_kernel(const int* __restrict__ rowptr, const int* __restrict__ col,
                    const float* __restrict__ colw, const float* __restrict__ dinv,
                    const float4* __restrict__ xw,
                    const float* __restrict__ lin_w,
                    const float* __restrict__ lin_b,
                    float* __restrict__ out, int n) {
    __shared__ float sw[CC * FF];
    __shared__ float sb[CC];
    int tid = threadIdx.x;
    for (int i = tid; i < CC * FF; i += 256) sw[i] = lin_w[i];
    if (tid < CC) sb[tid] = lin_b[tid];
    __syncthreads();

    int warp = (blockIdx.x * blockDim.x + tid) >> 5;
    int lane = tid & 31;
    if (warp >= n) return;

    float4 v = gather_row(rowptr, col, colw, dinv, xw, warp, lane);
    v.x = fmaxf(v.x, 0.f); v.y = fmaxf(v.y, 0.f);
    v.z = fmaxf(v.z, 0.f); v.w = fmaxf(v.w, 0.f);

    float logits[CC];
#pragma unroll
    for (int c = 0; c < CC; c++) {
        float4 w = *(const float4*)(sw + c * 128 + lane * 4);
        float p = v.x * w.x + v.y * w.y + v.z * w.z + v.w * w.w;
#pragma unroll
        for (int off = 16; off > 0; off >>= 1)
            p += __shfl_xor_sync(0xffffffffu, p, off);
        logits[c] = p + sb[c];
    }
    float m = logits[0];
#pragma unroll
    for (int c = 1; c < CC; c++) m = fmaxf(m, logits[c]);
    float se = 0.f;
#pragma unroll
    for (int c = 0; c < CC; c++) se += expf(logits[c] - m);
    float lse = m + logf(se);
    if (lane == 0) {
#pragma unroll
        for (int c = 0; c < CC; c++) out[warp * CC + c] = logits[c] - lse;
    }
}

// ---------------- launch ----------------------------------------------------
extern "C" void kernel_launch(void* const* d_in, const int* in_sizes, int n_in,
                              void* d_out, int out_size) {
    const float* x     = (const float*)d_in[0];
    const int*   ei    = (const int*)d_in[1];
    const float* W1    = (const float*)d_in[2];
    const float* wih1  = (const float*)d_in[3];
    const float* whh1  = (const float*)d_in[4];
    const float* bih1  = (const float*)d_in[5];
    const float* bhh1  = (const float*)d_in[6];
    const float* W2    = (const float*)d_in[7];
    const float* wih2  = (const float*)d_in[8];
    const float* whh2  = (const float*)d_in[9];
    const float* bih2  = (const float*)d_in[10];
    const float* bhh2  = (const float*)d_in[11];
    const float* lin_w = (const float*)d_in[12];
    const float* lin_b = (const float*)d_in[13];
    float* out = (float*)d_out;

    int n = in_sizes[0] / FF;   // 50000
    int e = in_sizes[1] / 2;    // 800000
    const int* src = ei;
    const int* dst = ei + e;

    float *pW1e, *pW2e, *pdinv, *pxw, *pagg, *pcolw;
    int *pcount, *prowptr, *pcursor, *pcol, *pbsum, *pboff;
    cudaGetSymbolAddress((void**)&pW1e, g_W1e);
    cudaGetSymbolAddress((void**)&pW2e, g_W2e);
    cudaGetSymbolAddress((void**)&pdinv, g_dinv);
    cudaGetSymbolAddress((void**)&pcount, g_count);
    cudaGetSymbolAddress((void**)&prowptr, g_rowptr);
    cudaGetSymbolAddress((void**)&pcursor, g_cursor);
    cudaGetSymbolAddress((void**)&pcol, g_col);
    cudaGetSymbolAddress((void**)&pcolw, g_colw);
    cudaGetSymbolAddress((void**)&pxw, g_xw);
    cudaGetSymbolAddress((void**)&pagg, g_agg);
    cudaGetSymbolAddress((void**)&pbsum, g_bsum);
    cudaGetSymbolAddress((void**)&pboff, g_boff);

    int nb = (n + SCAN_B - 1) / SCAN_B;  // 49
    int gemm_blocks = (n + 63) / 64;
    int ga_blocks   = (n * 32 + 255) / 256;

    // 1. evolve weights
    gru_kernel<<<FF, FF>>>(W1, wih1, whh1, bih1, bhh1, pW1e);
    gru_kernel<<<FF, FF>>>(W2, wih2, whh2, bih2, bhh2, pW2e);

    // 2. CSR build: histogram -> 3-pass scan -> fill
    cudaMemsetAsync(pcount, 0, n * sizeof(int));
    hist_kernel<<<(e + 255) / 256, 256>>>(dst, e, pcount);
    scan_blocks_kernel<<<nb, SCAN_B>>>(pcount, prowptr, pbsum, n);
    scan_tops_kernel<<<1, 64>>>(pbsum, pboff, prowptr, n, nb);
    scan_add_kernel<<<nb, SCAN_B>>>(pcount, pboff, prowptr, pcursor, pdinv, n);
    fill_kernel<<<(e + 255) / 256, 256>>>(src, dst, e, pdinv, pcursor, pcol, pcolw);

    // 3. layer 1
    gemm_nk128<false><<<gemm_blocks, 256>>>(x, pW1e, pxw, n);
    gather_kernel<<<ga_blocks, 256>>>(prowptr, pcol, pcolw, pdinv,
                                      (const float4*)pxw, (float4*)pagg, n);

    // 4. layer 2 (relu fused into GEMM A-load)
    gemm_nk128<true><<<gemm_blocks, 256>>>(pagg, pW2e, pxw, n);

    // 5. gather2 fused with relu -> linear -> log_softmax
    gather_final_kernel<<<ga_blocks, 256>>>(prowptr, pcol, pcolw, pdinv,
                                            (const float4*)pxw, lin_w, lin_b,
                                            out, n);
}

// round 13
// speedup vs baseline: 1.1864x; 1.0553x over previous
#include <cuda_runtime.h>
#include <math.h>
#include <stdint.h>

// Problem constants (fixed by the dataset)
#define NN 50000
#define FF 128
#define EE 800000
#define CC 10

#define SCAN_B 1024
#define SCAN_NB ((NN + SCAN_B - 1) / SCAN_B)   // 49

// ---------------- scratch (static device globals; no allocation) ----------
__device__ float g_W1e[FF * FF];
__device__ float g_W2e[FF * FF];
__device__ float g_dinv[NN];
__device__ int   g_count[NN];
__device__ int   g_rowptr[NN + 1];
__device__ int   g_cursor[NN];
__device__ int   g_bsum[SCAN_NB];
__device__ int   g_boff[SCAN_NB];
__device__ int2  g_ecw[EE];          // packed edge: {src, weight-bits}
__device__ float g_xw[NN * FF];
__device__ float g_agg[NN * FF];

// packed dual-fp32 FMA: d.lo += a.lo*b.lo, d.hi += a.hi*b.hi
__device__ __forceinline__ void fma2(unsigned long long& d,
                                     unsigned long long a,
                                     unsigned long long b) {
    asm("fma.rn.f32x2 %0, %1, %2, %0;" : "+l"(d) : "l"(a), "l"(b));
}
// pack {a, a} into a u64 operand
__device__ __forceinline__ unsigned long long dup2(float a) {
    unsigned long long r;
    asm("mov.b64 %0, {%1, %1};" : "=l"(r) : "f"(a));
    return r;
}

// ---------------- GRU weight evolution (both sets in one launch) -----------
__global__ void gru2x_kernel(const float* __restrict__ Wa, const float* __restrict__ wiha,
                             const float* __restrict__ whha, const float* __restrict__ biha,
                             const float* __restrict__ bhha, float* __restrict__ Woa,
                             const float* __restrict__ Wb, const float* __restrict__ wihb,
                             const float* __restrict__ whhb, const float* __restrict__ bihb,
                             const float* __restrict__ bhhb, float* __restrict__ Wob) {
    int set = blockIdx.x >> 7;          // 0..1
    int m = blockIdx.x & 127;
    int f = threadIdx.x;
    const float* W0  = set ? Wb   : Wa;
    const float* wih = set ? wihb : wiha;
    const float* whh = set ? whhb : whha;
    const float* bih = set ? bihb : biha;
    const float* bhh = set ? bhhb : bhha;
    float* Wout      = set ? Wob  : Woa;

    __shared__ float sW[FF];
    sW[f] = W0[m * FF + f];
    __syncthreads();

    const float* wr = wih + f * FF;
    const float* wz = wih + (f + FF) * FF;
    const float* wn = wih + (f + 2 * FF) * FF;
    const float* vr = whh + f * FF;
    const float* vz = whh + (f + FF) * FF;
    const float* vn = whh + (f + 2 * FF) * FF;

    float ir = 0.f, iz = 0.f, in_ = 0.f, hr = 0.f, hz = 0.f, hn = 0.f;
#pragma unroll 8
    for (int k = 0; k < FF; k++) {
        float a = sW[k];
        ir += a * wr[k]; iz += a * wz[k]; in_ += a * wn[k];
        hr += a * vr[k]; hz += a * vz[k]; hn += a * vn[k];
    }
    ir += bih[f];          iz += bih[f + FF];     in_ += bih[f + 2 * FF];
    hr += bhh[f];          hz += bhh[f + FF];     hn += bhh[f + 2 * FF];

    float r = 1.f / (1.f + expf(-(ir + hr)));
    float z = 1.f / (1.f + expf(-(iz + hz)));
    float nn = tanhf(in_ + r * hn);
    float h = sW[f];
    Wout[m * FF + f] = (1.f - z) * nn + z * h;
}

// ---------------- CSR build -------------------------------------------------
__global__ void hist_kernel(const int* __restrict__ dst, int e,
                            int* __restrict__ count) {
    int i = blockIdx.x * blockDim.x + threadIdx.x;
    if (i < e) atomicAdd(&count[dst[i]], 1);
}

__global__ void __launch_bounds__(SCAN_B)
scan_blocks_kernel(const int* __restrict__ count, int* __restrict__ rowptr,
                   int* __restrict__ bsum, int n) {
    __shared__ int warp_sums[32];
    int tid = threadIdx.x;
    int lane = tid & 31, wid = tid >> 5;
    int i = blockIdx.x * SCAN_B + tid;
    int c = (i < n) ? count[i] : 0;
    int v = c;
#pragma unroll
    for (int off = 1; off < 32; off <<= 1) {
        int t = __shfl_up_sync(0xffffffffu, v, off);
        if (lane >= off) v += t;
    }
    if (lane == 31) warp_sums[wid] = v;
    __syncthreads();
    if (tid < 32) {
        int w = warp_sums[tid];
#pragma unroll
        for (int off = 1; off < 32; off <<= 1) {
            int t = __shfl_up_sync(0xffffffffu, w, off);
            if (tid >= off) w += t;
        }
        warp_sums[tid] = w;
    }
    __syncthreads();
    int incl = v + (wid > 0 ? warp_sums[wid - 1] : 0);
    if (i < n) rowptr[i] = incl - c;
    if (tid == SCAN_B - 1) bsum[blockIdx.x] = incl;
}

__global__ void scan_tops_kernel(const int* __restrict__ bsum,
                                 int* __restrict__ boff,
                                 int* __restrict__ rowptr, int n, int nb) {
    int tid = threadIdx.x;  // 64 threads
    int c = (tid < nb) ? bsum[tid] : 0;
    int v = c;
#pragma unroll
    for (int off = 1; off < 32; off <<= 1) {
        int t = __shfl_up_sync(0xffffffffu, v, off);
        if ((tid & 31) >= off) v += t;
    }
    __shared__ int w0sum;
    if (tid == 31) w0sum = v;
    __syncthreads();
    int incl = v + ((tid >= 32) ? w0sum : 0);
    if (tid < nb) boff[tid] = incl - c;
    if (tid == nb - 1) rowptr[n] = incl;
}

__global__ void __launch_bounds__(SCAN_B)
scan_add_kernel(const int* __restrict__ count, const int* __restrict__ boff,
                int* __restrict__ rowptr, int* __restrict__ cursor,
                float* __restrict__ dinv, int n) {
    int i = blockIdx.x * SCAN_B + threadIdx.x;
    if (i >= n) return;
    int r = rowptr[i] + boff[blockIdx.x];
    rowptr[i] = r;
    cursor[i] = r;
    dinv[i] = rsqrtf((float)(count[i] + 1));
}

__global__ void fill_kernel(const int* __restrict__ src,
                            const int* __restrict__ dst, int e,
                            const float* __restrict__ dinv,
                            int* __restrict__ cursor,
                            int2* __restrict__ ecw) {
    int i = blockIdx.x * blockDim.x + threadIdx.x;
    if (i >= e) return;
    int s = src[i];
    int d = dst[i];
    int idx = atomicAdd(&cursor[d], 1);
    float w = __ldg(dinv + s) * __ldg(dinv + d);
    ecw[idx] = make_int2(s, __float_as_int(w));
}

// ---------------- gather core (row accumulate in registers) -----------------
__device__ __forceinline__ float4 gather_row(const int* __restrict__ rowptr,
                                             const int2* __restrict__ ecw,
                                             const float* __restrict__ dinv,
                                             const float4* __restrict__ xw,
                                             int row, int lane) {
    int beg = __ldg(rowptr + row);
    int end = __ldg(rowptr + row + 1);
    float di = __ldg(dinv + row);
    float wl = di * di;
    float4 v = xw[row * 32 + lane];
    float4 acc = make_float4(wl * v.x, wl * v.y, wl * v.z, wl * v.w);

    int e = beg;
    for (; e + 8 <= end; e += 8) {
        int2 m[8]; float4 a[8];
#pragma unroll
        for (int j = 0; j < 8; j++) m[j] = __ldg(ecw + e + j);
#pragma unroll
        for (int j = 0; j < 8; j++) a[j] = xw[m[j].x * 32 + lane];
#pragma unroll
        for (int j = 0; j < 8; j++) {
            float w = __int_as_float(m[j].y);
            acc.x += w * a[j].x;
            acc.y += w * a[j].y;
            acc.z += w * a[j].z;
            acc.w += w * a[j].w;
        }
    }
    for (; e + 4 <= end; e += 4) {
        int2 m0 = __ldg(ecw + e + 0), m1 = __ldg(ecw + e + 1);
        int2 m2 = __ldg(ecw + e + 2), m3 = __ldg(ecw + e + 3);
        float4 a0 = xw[m0.x * 32 + lane];
        float4 a1 = xw[m1.x * 32 + lane];
        float4 a2 = xw[m2.x * 32 + lane];
        float4 a3 = xw[m3.x * 32 + lane];
        float w0 = __int_as_float(m0.y), w1 = __int_as_float(m1.y);
        float w2 = __int_as_float(m2.y), w3 = __int_as_float(m3.y);
        acc.x += w0 * a0.x + w1 * a1.x + w2 * a2.x + w3 * a3.x;
        acc.y += w0 * a0.y + w1 * a1.y + w2 * a2.y + w3 * a3.y;
        acc.z += w0 * a0.z + w1 * a1.z + w2 * a2.z + w3 * a3.z;
        acc.w += w0 * a0.w + w1 * a1.w + w2 * a2.w + w3 * a3.w;
    }
    for (; e < end; e++) {
        int2 m0 = __ldg(ecw + e);
        float w0 = __int_as_float(m0.y);
        float4 a0 = xw[m0.x * 32 + lane];
        acc.x += w0 * a0.x; acc.y += w0 * a0.y;
        acc.z += w0 * a0.z; acc.w += w0 * a0.w;
    }
    return acc;
}

// ---------------- GEMM1: C[M,128] = A[M,128] @ W[128,128] ------------------
// BM=64, BK=32, 256 threads, FFMA2 packed accumulators (8 rows x 2 col-pairs).
__global__ void __launch_bounds__(256)
gemm_nk128(const float* __restrict__ A, const float* __restrict__ W,
           float* __restrict__ C, int M) {
    __shared__ float As[64][32];
    __shared__ float Bs[32][128];
    int tid = threadIdx.x;
    int tx = tid & 31;
    int ty = tid >> 5;
    int row0 = blockIdx.x * 64;

    unsigned long long acc[8][2];
#pragma unroll
    for (int i = 0; i < 8; i++) { acc[i][0] = 0ull; acc[i][1] = 0ull; }

    for (int k0 = 0; k0 < 128; k0 += 32) {
#pragma unroll
        for (int v = 0; v < 2; v++) {
            int u = tid + v * 256;
            int r = u >> 3, c4 = u & 7;
            int gr = row0 + r;
            float4 val = make_float4(0.f, 0.f, 0.f, 0.f);
            if (gr < M)
                val = *(const float4*)(A + gr * 128 + k0 + c4 * 4);
            *(float4*)&As[r][c4 * 4] = val;
        }
#pragma unroll
        for (int v = 0; v < 4; v++) {
            int u = tid + v * 256;
            int r = u >> 5, c4 = u & 31;
            *(float4*)&Bs[r][c4 * 4] = *(const float4*)(W + (k0 + r) * 128 + c4 * 4);
        }
        __syncthreads();
#pragma unroll
        for (int kk = 0; kk < 32; kk++) {
            ulonglong2 b01 = *(const ulonglong2*)&Bs[kk][tx * 4];
#pragma unroll
            for (int i = 0; i < 8; i++) {
                unsigned long long ad = dup2(As[ty * 8 + i][kk]);
                fma2(acc[i][0], ad, b01.x);
                fma2(acc[i][1], ad, b01.y);
            }
        }
        __syncthreads();
    }
#pragma unroll
    for (int i = 0; i < 8; i++) {
        int gr = row0 + ty * 8 + i;
        if (gr < M) {
            float4 o;
            o.x = __uint_as_float((unsigned)(acc[i][0]));
            o.y = __uint_as_float((unsigned)(acc[i][0] >> 32));
            o.z = __uint_as_float((unsigned)(acc[i][1]));
            o.w = __uint_as_float((unsigned)(acc[i][1] >> 32));
            *(float4*)(C + gr * 128 + tx * 4) = o;
        }
    }
}

// ---------------- fused: gather(layer1) + relu + GEMM(W2) ------------------
// Block gathers its 64 rows into As smem, then GEMMs against W (BK=16).
__global__ void __launch_bounds__(256)
gather_gemm_kernel(const int* __restrict__ rowptr, const int2* __restrict__ ecw,
                   const float* __restrict__ dinv, const float4* __restrict__ xw,
                   const float* __restrict__ W, float* __restrict__ C, int M) {
    __shared__ float As[64][128];   // 32 KB gathered rows (post-relu)
    __shared__ float Bs[16][128];   // 8 KB W tile
    int tid = threadIdx.x;
    int wid = tid >> 5, lane = tid & 31;
    int tx = lane, ty = wid;
    int row0 = blockIdx.x * 64;

    // phase 1: each warp gathers 8 rows
#pragma unroll 1
    for (int i = 0; i < 8; i++) {
        int r = wid * 8 + i;
        int row = row0 + r;
        if (row < M) {
            float4 v = gather_row(rowptr, ecw, dinv, xw, row, lane);
            v.x = fmaxf(v.x, 0.f); v.y = fmaxf(v.y, 0.f);
            v.z = fmaxf(v.z, 0.f); v.w = fmaxf(v.w, 0.f);
            *(float4*)&As[r][lane * 4] = v;
        }
    }
    __syncthreads();

    // phase 2: GEMM from smem A, BK=16
    unsigned long long acc[8][2];
#pragma unroll
    for (int i = 0; i < 8; i++) { acc[i][0] = 0ull; acc[i][1] = 0ull; }

    for (int k0 = 0; k0 < 128; k0 += 16) {
        // load Bs: 16x128 = 512 float4, 2 per thread
#pragma unroll
        for (int v = 0; v < 2; v++) {
            int u = tid + v * 256;
            int r = u >> 5, c4 = u & 31;
            *(float4*)&Bs[r][c4 * 4] = *(const float4*)(W + (k0 + r) * 128 + c4 * 4);
        }
        __syncthreads();
#pragma unroll
        for (int kk = 0; kk < 16; kk++) {
            ulonglong2 b01 = *(const ulonglong2*)&Bs[kk][tx * 4];
#pragma unroll
            for (int i = 0; i < 8; i++) {
                unsigned long long ad = dup2(As[ty * 8 + i][k0 + kk]);
                fma2(acc[i][0], ad, b01.x);
                fma2(acc[i][1], ad, b01.y);
            }
        }
        __syncthreads();
    }
#pragma unroll
    for (int i = 0; i < 8; i++) {
        int gr = row0 + ty * 8 + i;
        if (gr < M) {
            float4 o;
            o.x = __uint_as_float((unsigned)(acc[i][0]));
            o.y = __uint_as_float((unsigned)(acc[i][0] >> 32));
            o.z = __uint_as_float((unsigned)(acc[i][1]));
            o.w = __uint_as_float((unsigned)(acc[i][1] >> 32));
            *(float4*)(C + gr * 128 + tx * 4) = o;
        }
    }
}

// ---------------- gather (layer 2) fused with relu->linear->log_softmax -----
__global__ void __launch_bounds__(256)
gather_final_kernel(const int* __restrict__ rowptr, const int2* __restrict__ ecw,
                    const float* __restrict__ dinv, const float4* __restrict__ xw,
                    const float* __restrict__ lin_w,
                    const float* __restrict__ lin_b,
                    float* __restrict__ out, int n) {
    __shared__ float sw[CC * FF];
    __shared__ float sb[CC];
    int tid = threadIdx.x;
    for (int i = tid; i < CC * FF; i += 256) sw[i] = lin_w[i];
    if (tid < CC) sb[tid] = lin_b[tid];
    __syncthreads();

    int warp = (blockIdx.x * blockDim.x + tid) >> 5;
    int lane = tid & 31;
    if (warp >= n) return;

    float4 v = gather_row(rowptr, ecw, dinv, xw, warp, lane);
    v.x = fmaxf(v.x, 0.f); v.y = fmaxf(v.y, 0.f);
    v.z = fmaxf(v.z, 0.f); v.w = fmaxf(v.w, 0.f);

    float logits[CC];
#pragma unroll
    for (int c = 0; c < CC; c++) {
        float4 w = *(const float4*)(sw + c * 128 + lane * 4);
        float p = v.x * w.x + v.y * w.y + v.z * w.z + v.w * w.w;
#pragma unroll
        for (int off = 16; off > 0; off >>= 1)
            p += __shfl_xor_sync(0xffffffffu, p, off);
        logits[c] = p + sb[c];
    }
    float m = logits[0];
#pragma unroll
    for (int c = 1; c < CC; c++) m = fmaxf(m, logits[c]);
    float se = 0.f;
#pragma unroll
    for (int c = 0; c < CC; c++) se += expf(logits[c] - m);
    float lse = m + logf(se);
    if (lane == 0) {
#pragma unroll
        for (int c = 0; c < CC; c++) out[warp * CC + c] = logits[c] - lse;
    }
}

// ---------------- launch ----------------------------------------------------
extern "C" void kernel_launch(void* const* d_in, const int* in_sizes, int n_in,
                              void* d_out, int out_size) {
    const float* x     = (const float*)d_in[0];
    const int*   ei    = (const int*)d_in[1];
    const float* W1    = (const float*)d_in[2];
    const float* wih1  = (const float*)d_in[3];
    const float* whh1  = (const float*)d_in[4];
    const float* bih1  = (const float*)d_in[5];
    const float* bhh1  = (const float*)d_in[6];
    const float* W2    = (const float*)d_in[7];
    const float* wih2  = (const float*)d_in[8];
    const float* whh2  = (const float*)d_in[9];
    const float* bih2  = (const float*)d_in[10];
    const float* bhh2  = (const float*)d_in[11];
    const float* lin_w = (const float*)d_in[12];
    const float* lin_b = (const float*)d_in[13];
    float* out = (float*)d_out;

    int n = in_sizes[0] / FF;   // 50000
    int e = in_sizes[1] / 2;    // 800000
    const int* src = ei;
    const int* dst = ei + e;

    float *pW1e, *pW2e, *pdinv, *pxw, *pagg;
    int *pcount, *prowptr, *pcursor, *pbsum, *pboff;
    int2 *pecw;
    cudaGetSymbolAddress((void**)&pW1e, g_W1e);
    cudaGetSymbolAddress((void**)&pW2e, g_W2e);
    cudaGetSymbolAddress((void**)&pdinv, g_dinv);
    cudaGetSymbolAddress((void**)&pcount, g_count);
    cudaGetSymbolAddress((void**)&prowptr, g_rowptr);
    cudaGetSymbolAddress((void**)&pcursor, g_cursor);
    cudaGetSymbolAddress((void**)&pecw, g_ecw);
    cudaGetSymbolAddress((void**)&pxw, g_xw);
    cudaGetSymbolAddress((void**)&pagg, g_agg);
    cudaGetSymbolAddress((void**)&pbsum, g_bsum);
    cudaGetSymbolAddress((void**)&pboff, g_boff);

    int nb = (n + SCAN_B - 1) / SCAN_B;  // 49
    int gemm_blocks = (n + 63) / 64;
    int ga_blocks   = (n * 32 + 255) / 256;

    // 1. evolve both weight sets in one launch
    gru2x_kernel<<<2 * FF, FF>>>(W1, wih1, whh1, bih1, bhh1, pW1e,
                                 W2, wih2, whh2, bih2, bhh2, pW2e);

    // 2. CSR build: histogram -> 3-pass scan -> fill (packed records)
    cudaMemsetAsync(pcount, 0, n * sizeof(int));
    hist_kernel<<<(e + 255) / 256, 256>>>(dst, e, pcount);
    scan_blocks_kernel<<<nb, SCAN_B>>>(pcount, prowptr, pbsum, n);
    scan_tops_kernel<<<1, 64>>>(pbsum, pboff, prowptr, n, nb);
    scan_add_kernel<<<nb, SCAN_B>>>(pcount, pboff, prowptr, pcursor, pdinv, n);
    fill_kernel<<<(e + 255) / 256, 256>>>(src, dst, e, pdinv, pcursor, pecw);

    // 3. layer 1 GEMM: xw = x @ W1e
    gemm_nk128<<<gemm_blocks, 256>>>(x, pW1e, pxw, n);

    // 4. fused: gather(layer1) + relu + GEMM(W2e) -> agg
    gather_gemm_kernel<<<gemm_blocks, 256>>>(prowptr, pecw, pdinv,
                                             (const float4*)pxw, pW2e, pagg, n);

    // 5. gather2 fused with relu -> linear -> log_softmax
    gather_final_kernel<<<ga_blocks, 256>>>(prowptr, pecw, pdinv,
                                            (const float4*)pagg, lin_w, lin_b,
                                            out, n);
}